// round 15
// baseline (speedup 1.0000x reference)
#include <cuda_runtime.h>
#include <cuda_fp16.h>
#include <cstdint>

#define U_N 200000
#define M_N 100000
#define E_N 2000000
#define HD 64
#define CN 7
#define NTOT (U_N + M_N)

// ---------------- device scratch (static; zero-initialized at module load) ----------------
// d_deg and d_lb_flag are re-zeroed by the fill phase of k_scan_fill each call,
// so every graph replay starts clean. d_bar is a monotonic ticket barrier
// counter (never reset; generation = ticket / gridDim).
__device__ int d_deg[NTOT];
__device__ int d_bar;
__device__ int d_off_u[U_N + 1];
__device__ int d_off_m[M_N + 1];
__device__ int d_cur_u[U_N];
__device__ int d_cur_m[M_N];
__device__ int d_nbr_u[E_N];
__device__ int d_nbr_m[E_N];
__device__ volatile int d_lb_flag[512];
__device__ int d_lb_agg[512];
__device__ int d_lb_inc[512];
// f16 feature buffers: [N][64] halves = uint4[N][8]; +128 rows pad for MMA tile tails
__device__ uint4 d_x16_u[(size_t)(U_N + 128) * 8];
__device__ uint4 d_x16_m[(size_t)(M_N + 128) * 8];
__device__ uint4 d_agg16_u[(size_t)(U_N + 128) * 8];
__device__ uint4 d_agg16_m[(size_t)(M_N + 128) * 8];
__device__ uint4 d_h1_u[(size_t)(U_N + 128) * 8];
__device__ uint4 d_h1_m[(size_t)(M_N + 128) * 8];
// f16 final layer-2 outputs (classifier inputs)
__device__ uint4 d_u2h[(size_t)U_N * 8];
__device__ uint4 d_m2h[(size_t)M_N * 8];

// ---------------- generic helpers ----------------
__device__ __forceinline__ int ldidx(const void* p, int i, int f64) {
    return f64 ? (int)((const long long*)p)[i] : ((const int*)p)[i];
}
__device__ __forceinline__ int detect64(const int* uw) { return uw[3] == 0; }
__device__ __forceinline__ uint2 f4_to_h4(float4 v) {
    __half2 a = __floats2half2_rn(v.x, v.y);
    __half2 b = __floats2half2_rn(v.z, v.w);
    uint2 r;
    r.x = *reinterpret_cast<unsigned int*>(&a);
    r.y = *reinterpret_cast<unsigned int*>(&b);
    return r;
}
__device__ __forceinline__ __half2 u2h(unsigned int x) {
    return *reinterpret_cast<__half2*>(&x);
}
__device__ __forceinline__ void acc_h4(float4& acc, uint2 raw) {
    float2 fa = __half22float2(u2h(raw.x)), fb = __half22float2(u2h(raw.y));
    acc.x += fa.x; acc.y += fa.y; acc.z += fb.x; acc.w += fb.y;
}
__device__ __forceinline__ uint32_t smem_u32(const void* p) {
    uint32_t a;
    asm("{ .reg .u64 t; cvta.to.shared.u64 t, %1; cvt.u32.u64 %0, t; }" : "=r"(a) : "l"(p));
    return a;
}

// ---------------- mma.sync helpers (baseline PTX, sm_80+: legal at compute_103) ----------------
#define LDSM_X4(r, addr) \
    asm volatile("ldmatrix.sync.aligned.m8n8.x4.shared.b16 {%0,%1,%2,%3}, [%4];" \
                 : "=r"((r)[0]), "=r"((r)[1]), "=r"((r)[2]), "=r"((r)[3]) : "r"(addr))
#define LDSM_X4T(r, addr) \
    asm volatile("ldmatrix.sync.aligned.m8n8.x4.trans.shared.b16 {%0,%1,%2,%3}, [%4];" \
                 : "=r"((r)[0]), "=r"((r)[1]), "=r"((r)[2]), "=r"((r)[3]) : "r"(addr))
#define LDSM_X2T(r0, r1, addr) \
    asm volatile("ldmatrix.sync.aligned.m8n8.x2.trans.shared.b16 {%0,%1}, [%2];" \
                 : "=r"(r0), "=r"(r1) : "r"(addr))
#define MMA16816(c, a, b0, b1) \
    asm volatile("mma.sync.aligned.m16n8k16.row.col.f32.f16.f16.f32 " \
                 "{%0,%1,%2,%3}, {%4,%5,%6,%7}, {%8,%9}, {%0,%1,%2,%3};" \
                 : "+f"((c)[0]), "+f"((c)[1]), "+f"((c)[2]), "+f"((c)[3]) \
                 : "r"((a)[0]), "r"((a)[1]), "r"((a)[2]), "r"((a)[3]), "r"(b0), "r"(b1))

// ---------------- launch 0: user gather + movie projection + degree count ----------------
__global__ __launch_bounds__(256) void k_prep(
    const int* uw, const void* unid, const void* mnid,
    const float* ue, const float* mx, const float* W, const float* bb,
    const float* memb, const void* es, const void* ed,
    int U, int M, int F, int E, int GG, int GM, int GC) {
    __shared__ float2 sW[32 * 32];
    int f64 = detect64(uw);
    if ((int)blockIdx.x < GG) {
        // x_user(f16) = user_emb[user_node_id]; thread = 8 floats -> 1 uint4 store
        int j = blockIdx.x * 256 + threadIdx.x;
        if (j < U * 8) {
            int node = j >> 3, q8 = j & 7;
            int uid = ldidx(unid, node, f64);
            const float4* base = reinterpret_cast<const float4*>(ue) + (size_t)uid * 16;
            uint2 lo = f4_to_h4(base[2 * q8]);
            uint2 hi = f4_to_h4(base[2 * q8 + 1]);
            uint4 pkt;
            pkt.x = lo.x; pkt.y = lo.y; pkt.z = hi.x; pkt.w = hi.y;
            d_x16_u[(size_t)node * 8 + q8] = pkt;
        }
    } else if ((int)blockIdx.x < GG + GM) {
        // x_movie(f16) = movie_x @ w_movie + b + movie_emb[id]
        for (int idx = threadIdx.x; idx < F * 32; idx += 256) {
            int f = idx >> 5, t = idx & 31;
            sW[idx] = make_float2(W[f * HD + t], W[f * HD + t + 32]);
        }
        __syncthreads();
        int lane = threadIdx.x & 31, warp = threadIdx.x >> 5;
        int mb = blockIdx.x - GG;
        __half* xm16 = reinterpret_cast<__half*>(d_x16_m);
        for (int m = mb * 8 + warp; m < M; m += GM * 8) {
            float mxv = (lane < F) ? mx[(size_t)m * F + lane] : 0.f;
            int mid = ldidx(mnid, m, f64);
            float acc0 = bb[lane] + memb[(size_t)mid * HD + lane];
            float acc1 = bb[lane + 32] + memb[(size_t)mid * HD + lane + 32];
            for (int f = 0; f < F; f++) {
                float v = __shfl_sync(0xffffffffu, mxv, f);
                float2 wv = sW[f * 32 + lane];
                acc0 += v * wv.x;
                acc1 += v * wv.y;
            }
            xm16[(size_t)m * HD + lane] = __float2half_rn(acc0);
            xm16[(size_t)m * HD + lane + 32] = __float2half_rn(acc1);
        }
    } else {
        int cb = blockIdx.x - (GG + GM);
        for (int e = cb * 256 + threadIdx.x; e < E; e += GC * 256) {
            atomicAdd(&d_deg[ldidx(es, e, f64)], 1);
            atomicAdd(&d_deg[U + ldidx(ed, e, f64)], 1);
        }
    }
}

// ---------------- launch 1: fused scan (decoupled lookback) + global barrier + fill ----------------
__global__ __launch_bounds__(1024) void k_scan_fill(const int* uw, const void* es,
                                                    const void* ed, int U, int M,
                                                    int E) {
    __shared__ int sh[1024];
    __shared__ int sRun;
    int n = U + M;
    int tid = threadIdx.x, bid = blockIdx.x;
    int base = bid * 4096 + tid * 4;
    int4 v = make_int4(0, 0, 0, 0);
    if (base + 3 < n)
        v = *reinterpret_cast<const int4*>(d_deg + base);
    else {
        if (base < n) v.x = d_deg[base];
        if (base + 1 < n) v.y = d_deg[base + 1];
        if (base + 2 < n) v.z = d_deg[base + 2];
    }
    int loc = v.x + v.y + v.z + v.w;
    sh[tid] = loc;
    __syncthreads();
    for (int o = 1; o < 1024; o <<= 1) {
        int a = (tid >= o) ? sh[tid - o] : 0;
        __syncthreads();
        sh[tid] += a;
        __syncthreads();
    }
    int incl = sh[tid];
    int bsum = sh[1023];
    if (tid == 0) {
        int run = 0;
        if (bid == 0) {
            d_lb_inc[0] = bsum;
            __threadfence();
            d_lb_flag[0] = 2;
        } else {
            d_lb_agg[bid] = bsum;
            __threadfence();
            d_lb_flag[bid] = 1;
            int p = bid - 1;
            while (true) {
                int f;
                while ((f = d_lb_flag[p]) == 0) {}
                __threadfence();
                if (f == 2) { run += d_lb_inc[p]; break; }
                run += d_lb_agg[p];
                p--;
            }
            d_lb_inc[bid] = run + bsum;
            __threadfence();
            d_lb_flag[bid] = 2;
        }
        sRun = run;
    }
    __syncthreads();
    int e = sRun + incl - loc;
    int vv[4] = {v.x, v.y, v.z, v.w};
#pragma unroll
    for (int w = 0; w < 4; w++) {
        int gi = base + w;
        if (gi < n) {
            if (gi < U) { d_off_u[gi] = e; d_cur_u[gi] = e; }
            else { d_off_m[gi - U] = e - E; d_cur_m[gi - U] = e - E; }
        }
        e += vv[w];
    }
    if (bid == 0 && tid == 0) { d_off_u[U] = E; d_off_m[M] = E; }

    // ---- global barrier (monotonic ticket; all blocks resident: grid <= 148) ----
    __threadfence();
    __syncthreads();
    if (tid == 0) {
        int ticket = atomicAdd(&d_bar, 1);
        int target = (ticket / (int)gridDim.x + 1) * (int)gridDim.x;
        while (*(volatile int*)&d_bar < target) {}
    }
    __syncthreads();
    __threadfence();

    // ---- fill phase + scratch re-zero for next replay ----
    int f64 = detect64(uw);
    int nth = gridDim.x * 1024;
    int gtid = bid * 1024 + tid;
    for (int ee = gtid; ee < E; ee += nth) {
        int s = ldidx(es, ee, f64);
        int d = ldidx(ed, ee, f64);
        d_nbr_u[atomicAdd(&d_cur_u[s], 1)] = d;
        d_nbr_m[atomicAdd(&d_cur_m[d], 1)] = s;
    }
    for (int i = gtid; i < NTOT + 512; i += nth) {
        if (i < NTOT) d_deg[i] = 0;
        else d_lb_flag[i - NTOT] = 0;
    }
}

// ---------------- gather: f16 src rows, quad-wise HADD2 + fp32 accumulate, f16 store ----------------
__global__ __launch_bounds__(256) void k_gather(const uint2* __restrict__ src,
                                                uint2* __restrict__ dst,
                                                const int* __restrict__ off,
                                                const int* __restrict__ nbr,
                                                int n_dst) {
    int lane = threadIdx.x & 31, warp = threadIdx.x >> 5;
    int half = lane >> 4, l16 = lane & 15;
    for (int i = blockIdx.x * 8 + warp; i < n_dst; i += gridDim.x * 8) {
        int s0 = off[i], s1 = off[i + 1];
        float4 acc = make_float4(0.f, 0.f, 0.f, 0.f);
        for (int j = s0; j < s1; j += 32) {
            int myn = (j + lane < s1) ? nbr[j + lane] : 0;
            int cnt = min(32, s1 - j);
            int jj = 0;
            for (; jj + 8 <= cnt; jj += 8) {
                int n0 = __shfl_sync(0xffffffffu, myn, jj + half);
                int n1 = __shfl_sync(0xffffffffu, myn, jj + 2 + half);
                int n2 = __shfl_sync(0xffffffffu, myn, jj + 4 + half);
                int n3 = __shfl_sync(0xffffffffu, myn, jj + 6 + half);
                uint2 v0 = src[(size_t)n0 * 16 + l16];
                uint2 v1 = src[(size_t)n1 * 16 + l16];
                uint2 v2 = src[(size_t)n2 * 16 + l16];
                uint2 v3 = src[(size_t)n3 * 16 + l16];
                // quad-wise f16 partial sum (6 HADD2), single convert to fp32
                __half2 slo = __hadd2(__hadd2(u2h(v0.x), u2h(v1.x)),
                                      __hadd2(u2h(v2.x), u2h(v3.x)));
                __half2 shi = __hadd2(__hadd2(u2h(v0.y), u2h(v1.y)),
                                      __hadd2(u2h(v2.y), u2h(v3.y)));
                float2 flo = __half22float2(slo);
                float2 fhi = __half22float2(shi);
                acc.x += flo.x; acc.y += flo.y; acc.z += fhi.x; acc.w += fhi.y;
            }
            for (; jj + 2 <= cnt; jj += 2) {
                int nn = __shfl_sync(0xffffffffu, myn, jj + half);
                acc_h4(acc, src[(size_t)nn * 16 + l16]);
            }
            if (jj < cnt) {
                int nn = __shfl_sync(0xffffffffu, myn, cnt - 1);
                if (half == 0) acc_h4(acc, src[(size_t)nn * 16 + l16]);
            }
        }
        acc.x += __shfl_xor_sync(0xffffffffu, acc.x, 16);
        acc.y += __shfl_xor_sync(0xffffffffu, acc.y, 16);
        acc.z += __shfl_xor_sync(0xffffffffu, acc.z, 16);
        acc.w += __shfl_xor_sync(0xffffffffu, acc.w, 16);
        if (half == 0) {
            float inv = 1.f / (float)max(s1 - s0, 1);
            dst[(size_t)i * 16 + l16] = f4_to_h4(
                make_float4(acc.x * inv, acc.y * inv, acc.z * inv, acc.w * inv));
        }
    }
}

// ---------------- mma.sync xform: out = [agg16|xd16][128 x 128k] @ [Wl;Wr][128 x 64] + b ----------------
#define XF_SA 0
#define XF_SB 34816                  /* 128 * 272 */
#define XF_BIAS (XF_SB + 18432)      /* 128 * 144 */
#define XF_SMEM (XF_BIAS + 256)
__global__ __launch_bounds__(128) void k_xform_mma(
    const uint4* __restrict__ agg16U, const uint4* __restrict__ xd16U,
    const uint4* __restrict__ agg16M, const uint4* __restrict__ xd16M,
    const float* __restrict__ WlU, const float* __restrict__ WrU,
    const float* __restrict__ blU,
    const float* __restrict__ WlM, const float* __restrict__ WrM,
    const float* __restrict__ blM,
    __half* __restrict__ out16U, __half* __restrict__ out16M,
    int NU, int NM, int XU, int doRelu) {
    extern __shared__ char smem[];
    int t = threadIdx.x;
    int lane = t & 31, w = t >> 5;

    int segU = (int)blockIdx.x < XU;
    const uint4* agg = segU ? agg16U : agg16M;
    const uint4* xd = segU ? xd16U : xd16M;
    const float* Wl = segU ? WlU : WlM;
    const float* Wr = segU ? WrU : WrM;
    const float* bl = segU ? blU : blM;
    __half* out16 = segU ? out16U : out16M;
    int N = segU ? NU : NM;
    int n0 = (segU ? blockIdx.x : blockIdx.x - XU) * 128;

    // stage A: node n0+t -> sA row t ([agg 64 | xd 64] halves), stride 272B
    {
        const uint4* ar = agg + (size_t)(n0 + t) * 8;
        const uint4* xr = xd + (size_t)(n0 + t) * 8;
        uint4* rowA = reinterpret_cast<uint4*>(smem + XF_SA + t * 272);
#pragma unroll
        for (int q = 0; q < 8; q++) rowA[q] = ar[q];
#pragma unroll
        for (int q = 0; q < 8; q++) rowA[8 + q] = xr[q];
    }
    // stage B: k row t -> sB[t][n] = (t<64 ? Wl[t][n] : Wr[t-64][n]) f16, stride 144B
    {
        const float* Wg = (t < 64) ? (Wl + t * HD) : (Wr + (t - 64) * HD);
        uint4* rowB = reinterpret_cast<uint4*>(smem + XF_SB + t * 144);
#pragma unroll
        for (int q = 0; q < 8; q++) {
            float4 w0 = reinterpret_cast<const float4*>(Wg)[2 * q];
            float4 w1 = reinterpret_cast<const float4*>(Wg)[2 * q + 1];
            uint2 lo = f4_to_h4(w0), hi = f4_to_h4(w1);
            uint4 pkt;
            pkt.x = lo.x; pkt.y = lo.y; pkt.z = hi.x; pkt.w = hi.y;
            rowB[q] = pkt;
        }
    }
    float* sbias = reinterpret_cast<float*>(smem + XF_BIAS);
    if (t < 64) sbias[t] = bl[t];
    __syncthreads();

    uint32_t smem32 = smem_u32(smem);
    float acc[2][8][4];
#pragma unroll
    for (int mt = 0; mt < 2; mt++)
#pragma unroll
        for (int nt = 0; nt < 8; nt++)
#pragma unroll
            for (int c = 0; c < 4; c++) acc[mt][nt][c] = 0.f;

    uint32_t aAddr0, aAddr1, bAddr;
    {
        int r = lane & 15;
        int cb = (lane >> 4) * 16;
        aAddr0 = smem32 + XF_SA + (uint32_t)(w * 32 + r) * 272 + cb;
        aAddr1 = aAddr0 + 16 * 272;
        int quad = lane >> 3, i = lane & 7;
        int row = (quad & 1) * 8 + i;
        int colb = (quad >> 1) * 16;
        bAddr = smem32 + XF_SB + (uint32_t)row * 144 + colb;
    }

#pragma unroll
    for (int kk = 0; kk < 8; kk++) {
        uint32_t a0[4], a1[4];
        LDSM_X4(a0, aAddr0 + kk * 32);
        LDSM_X4(a1, aAddr1 + kk * 32);
#pragma unroll
        for (int nt2 = 0; nt2 < 4; nt2++) {
            uint32_t b[4];
            LDSM_X4T(b, bAddr + kk * 2304 + nt2 * 32);
            MMA16816(acc[0][2 * nt2], a0, b[0], b[1]);
            MMA16816(acc[0][2 * nt2 + 1], a0, b[2], b[3]);
            MMA16816(acc[1][2 * nt2], a1, b[0], b[1]);
            MMA16816(acc[1][2 * nt2 + 1], a1, b[2], b[3]);
        }
    }

    // epilogue: fragment layout m16n8 -> rows g,g+8, cols 2*q4,+1
    int g = lane >> 2, q4 = lane & 3;
#pragma unroll
    for (int mt = 0; mt < 2; mt++) {
        int r0 = n0 + w * 32 + mt * 16 + g;
        int r1 = r0 + 8;
#pragma unroll
        for (int nt = 0; nt < 8; nt++) {
            int col = nt * 8 + q4 * 2;
            float b0 = sbias[col], b1 = sbias[col + 1];
            float o00 = acc[mt][nt][0] + b0, o01 = acc[mt][nt][1] + b1;
            float o10 = acc[mt][nt][2] + b0, o11 = acc[mt][nt][3] + b1;
            if (doRelu) {
                o00 = fmaxf(o00, 0.f); o01 = fmaxf(o01, 0.f);
                o10 = fmaxf(o10, 0.f); o11 = fmaxf(o11, 0.f);
            }
            if (r0 < N) {
                __half2 h = __floats2half2_rn(o00, o01);
                *reinterpret_cast<__half2*>(out16 + (size_t)r0 * HD + col) = h;
            }
            if (r1 < N) {
                __half2 h = __floats2half2_rn(o10, o11);
                *reinterpret_cast<__half2*>(out16 + (size_t)r1 * HD + col) = h;
            }
        }
    }
}

// ---------------- final: mma edge classifier (warp-per-16-edges, high occupancy) ----------------
#define CLS_WARPS 4
__global__ __launch_bounds__(128) void k_classify_mma(
    const int* uw, const void* els, const void* eld,
    const float* __restrict__ W, const float* __restrict__ b,
    const uint4* __restrict__ u2h, const uint4* __restrict__ m2h,
    float* __restrict__ out, int EL, int GC) {
    __shared__ __align__(16) char sA[CLS_WARPS][16 * 272];  // 17408B
    __shared__ __align__(16) __half sB[128 * 8];            // [k][8] (7 used)
    __shared__ float sbias[8];
    int t = threadIdx.x, lane = t & 31, w = t >> 5;

    // stage B (cls_W f16, padded to 8 cols) + bias
    {
        const float* wr = W + t * CN;
        __half h[8];
#pragma unroll
        for (int c = 0; c < CN; c++) h[c] = __float2half_rn(wr[c]);
        h[7] = __float2half_rn(0.f);
        *reinterpret_cast<uint4*>(&sB[t * 8]) = *reinterpret_cast<uint4*>(h);
    }
    if (t < 8) sbias[t] = (t < CN) ? b[t] : 0.f;
    __syncthreads();

    // hoist B fragments (8 k-steps x 2 regs), reused for every edge tile
    uint32_t smemB = smem_u32(sB);
    uint32_t bf0[8], bf1[8];
#pragma unroll
    for (int kk = 0; kk < 8; kk++)
        LDSM_X2T(bf0[kk], bf1[kk], smemB + (uint32_t)(kk * 16 + (lane & 15)) * 16);

    int f64 = detect64(uw);
    uint32_t sAbase = smem_u32(&sA[w][0]);
    int quarter = lane >> 3, chunk = lane & 7;
    int g = lane >> 2, q4 = lane & 3, col = 2 * q4;
    float b0 = sbias[col], b1 = sbias[col < 6 ? col + 1 : 7];
    uint32_t a0base = sAbase + (uint32_t)(lane & 15) * 272 + (uint32_t)(lane >> 4) * 16;

    int ntile = (EL + 15) >> 4;
    for (int tile = blockIdx.x * CLS_WARPS + w; tile < ntile; tile += GC * CLS_WARPS) {
        int tbase = tile << 4;
        int ge = tbase + lane;
        int sI = 0, dI = 0;
        if (lane < 16 && ge < EL) {
            sI = ldidx(els, ge, f64);
            dI = ldidx(eld, ge, f64);
        }
        // stage A: 4 reps x 4 edges; 8 lanes per edge load u-row + m-row (128B each)
#pragma unroll
        for (int rep = 0; rep < 4; rep++) {
            int ei = rep * 4 + quarter;
            int s = __shfl_sync(0xffffffffu, sI, ei);
            int d = __shfl_sync(0xffffffffu, dI, ei);
            uint4 uv = u2h[(size_t)s * 8 + chunk];
            uint4 mv = m2h[(size_t)d * 8 + chunk];
            *reinterpret_cast<uint4*>(&sA[w][ei * 272 + chunk * 16]) = uv;
            *reinterpret_cast<uint4*>(&sA[w][ei * 272 + 128 + chunk * 16]) = mv;
        }
        __syncwarp();

        float acc[4] = {0.f, 0.f, 0.f, 0.f};
#pragma unroll
        for (int kk = 0; kk < 8; kk++) {
            uint32_t a0[4];
            LDSM_X4(a0, a0base + kk * 32);
            MMA16816(acc, a0, bf0[kk], bf1[kk]);
        }
        __syncwarp();

        // epilogue: rows g, g+8 of the m16 tile = edges; cols 2q4, 2q4+1
        int e0 = tbase + g;
        int e1 = e0 + 8;
        float o00 = acc[0] + b0, o01 = acc[1] + b1;
        float o10 = acc[2] + b0, o11 = acc[3] + b1;
        if (e0 < EL) {
            out[(size_t)e0 * CN + col] = o00;
            if (col < 6) out[(size_t)e0 * CN + col + 1] = o01;
        }
        if (e1 < EL) {
            out[(size_t)e1 * CN + col] = o10;
            if (col < 6) out[(size_t)e1 * CN + col + 1] = o11;
        }
    }
}

// ---------------- host launch ----------------
extern "C" void kernel_launch(void* const* d_in, const int* in_sizes, int n_in,
                              void* d_out, int out_size) {
    const int* uw = (const int*)d_in[0];
    const void* unid = d_in[0];
    const void* mnid = d_in[1];
    const float* movie_x = (const float*)d_in[2];
    const void* esrc = d_in[3];
    const void* edst = d_in[4];
    const void* elsrc = d_in[5];
    const void* eldst = d_in[6];
    const float* user_emb = (const float*)d_in[7];
    const float* movie_emb = (const float*)d_in[8];
    const float* w_movie = (const float*)d_in[9];
    const float* b_movie = (const float*)d_in[10];

    int U = in_sizes[0];
    int M = in_sizes[1];
    int E = in_sizes[3];
    int EL = in_sizes[5];
    int F = in_sizes[2] / M;
    (void)n_in; (void)out_size;

    void *p_off_u, *p_off_m, *p_nbr_u, *p_nbr_m;
    void *p_x16u, *p_x16m, *p_agg16u, *p_agg16m, *p_h1u, *p_h1m, *p_u2h, *p_m2h;
    cudaGetSymbolAddress(&p_off_u, d_off_u);
    cudaGetSymbolAddress(&p_off_m, d_off_m);
    cudaGetSymbolAddress(&p_nbr_u, d_nbr_u);
    cudaGetSymbolAddress(&p_nbr_m, d_nbr_m);
    cudaGetSymbolAddress(&p_x16u, d_x16_u);
    cudaGetSymbolAddress(&p_x16m, d_x16_m);
    cudaGetSymbolAddress(&p_agg16u, d_agg16_u);
    cudaGetSymbolAddress(&p_agg16m, d_agg16_m);
    cudaGetSymbolAddress(&p_h1u, d_h1_u);
    cudaGetSymbolAddress(&p_h1m, d_h1_m);
    cudaGetSymbolAddress(&p_u2h, d_u2h);
    cudaGetSymbolAddress(&p_m2h, d_m2h);

    cudaFuncSetAttribute(k_xform_mma, cudaFuncAttributeMaxDynamicSharedMemorySize,
                         XF_SMEM);

    const int* off_u = (const int*)p_off_u;
    const int* off_m = (const int*)p_off_m;
    const int* nbr_u = (const int*)p_nbr_u;
    const int* nbr_m = (const int*)p_nbr_m;

    // 0: prep (f16 x_user / x_movie + degree count)
    int GG = (U * 8 + 255) / 256;
    int GM = 1024;
    int GC = 2048;
    k_prep<<<GG + GM + GC, 256>>>(uw, unid, mnid, user_emb, movie_x, w_movie,
                                  b_movie, movie_emb, esrc, edst,
                                  U, M, F, E, GG, GM, GC);
    // 1: fused scan + barrier + fill (+ deg/lb re-zero)
    int NB = (U + M + 4095) / 4096;  // 74 blocks <= 148 SMs: all resident
    k_scan_fill<<<NB, 1024>>>(uw, esrc, edst, U, M, E);

    const int GB = 1776;
    int XU = (U + 127) / 128, XM = (M + 127) / 128;

    // 2: gather layer1 U (agg16_u <- x16_m)
    k_gather<<<GB, 256>>>((const uint2*)p_x16m, (uint2*)p_agg16u, off_u, nbr_u, U);
    // 3: gather layer1 M (agg16_m <- x16_u)  [ncu target]
    k_gather<<<GB, 256>>>((const uint2*)p_x16u, (uint2*)p_agg16m, off_m, nbr_m, M);
    // 4: mma xform layer1 (relu) -> h1 f16
    k_xform_mma<<<XU + XM, 128, XF_SMEM>>>(
        (const uint4*)p_agg16u, (const uint4*)p_x16u,
        (const uint4*)p_agg16m, (const uint4*)p_x16m,
        (const float*)d_in[14], (const float*)d_in[16], (const float*)d_in[15],
        (const float*)d_in[11], (const float*)d_in[13], (const float*)d_in[12],
        (__half*)p_h1u, (__half*)p_h1m, U, M, XU, 1);
    // 5: gather layer2 U (agg16_u <- h1_m)
    k_gather<<<GB, 256>>>((const uint2*)p_h1m, (uint2*)p_agg16u, off_u, nbr_u, U);
    // 6: gather layer2 M (agg16_m <- h1_u)
    k_gather<<<GB, 256>>>((const uint2*)p_h1u, (uint2*)p_agg16m, off_m, nbr_m, M);
    // 7: mma xform layer2 (no relu) -> u2h/m2h f16
    k_xform_mma<<<XU + XM, 128, XF_SMEM>>>(
        (const uint4*)p_agg16u, (const uint4*)p_h1u,
        (const uint4*)p_agg16m, (const uint4*)p_h1m,
        (const float*)d_in[20], (const float*)d_in[22], (const float*)d_in[21],
        (const float*)d_in[17], (const float*)d_in[19], (const float*)d_in[18],
        (__half*)p_u2h, (__half*)p_m2h, U, M, XU, 0);
    // 8: mma classifier
    int GCC = 1480;
    k_classify_mma<<<GCC, 128>>>(uw, elsrc, eldst, (const float*)d_in[23],
                                 (const float*)d_in[24],
                                 (const uint4*)p_u2h, (const uint4*)p_m2h,
                                 (float*)d_out, EL, GCC);
}

// round 16
// speedup vs baseline: 1.0309x; 1.0309x over previous
#include <cuda_runtime.h>
#include <cuda_fp16.h>
#include <cstdint>

#define U_N 200000
#define M_N 100000
#define E_N 2000000
#define HD 64
#define CN 7
#define NTOT (U_N + M_N)

// ---------------- device scratch (static; zero-initialized at module load) ----------------
// d_deg and d_lb_flag are re-zeroed at the END of every kernel_launch (tail
// blocks of the classifier), so every graph replay starts from a clean state.
__device__ int d_deg[NTOT];
__device__ int d_off_u[U_N + 1];
__device__ int d_off_m[M_N + 1];
__device__ int d_cur_u[U_N];
__device__ int d_cur_m[M_N];
__device__ int d_nbr_u[E_N];
__device__ int d_nbr_m[E_N];
__device__ volatile int d_lb_flag[512];
__device__ int d_lb_agg[512];
__device__ int d_lb_inc[512];
// f16 feature buffers: [N][64] halves = uint4[N][8]; +128 rows pad for MMA tile tails
__device__ uint4 d_x16_u[(size_t)(U_N + 128) * 8];
__device__ uint4 d_x16_m[(size_t)(M_N + 128) * 8];
__device__ uint4 d_agg16_u[(size_t)(U_N + 128) * 8];
__device__ uint4 d_agg16_m[(size_t)(M_N + 128) * 8];
__device__ uint4 d_h1_u[(size_t)(U_N + 128) * 8];
__device__ uint4 d_h1_m[(size_t)(M_N + 128) * 8];
// f16 final layer-2 outputs (classifier inputs)
__device__ uint4 d_u2h[(size_t)U_N * 8];
__device__ uint4 d_m2h[(size_t)M_N * 8];

// ---------------- generic helpers ----------------
__device__ __forceinline__ int ldidx(const void* p, int i, int f64) {
    return f64 ? (int)((const long long*)p)[i] : ((const int*)p)[i];
}
__device__ __forceinline__ int detect64(const int* uw) { return uw[3] == 0; }
__device__ __forceinline__ uint2 f4_to_h4(float4 v) {
    __half2 a = __floats2half2_rn(v.x, v.y);
    __half2 b = __floats2half2_rn(v.z, v.w);
    uint2 r;
    r.x = *reinterpret_cast<unsigned int*>(&a);
    r.y = *reinterpret_cast<unsigned int*>(&b);
    return r;
}
__device__ __forceinline__ __half2 u2h(unsigned int x) {
    return *reinterpret_cast<__half2*>(&x);
}
__device__ __forceinline__ void acc_h4(float4& acc, uint2 raw) {
    float2 fa = __half22float2(u2h(raw.x)), fb = __half22float2(u2h(raw.y));
    acc.x += fa.x; acc.y += fa.y; acc.z += fb.x; acc.w += fb.y;
}
__device__ __forceinline__ uint32_t smem_u32(const void* p) {
    uint32_t a;
    asm("{ .reg .u64 t; cvta.to.shared.u64 t, %1; cvt.u32.u64 %0, t; }" : "=r"(a) : "l"(p));
    return a;
}

// ---------------- mma.sync helpers (baseline PTX, sm_80+: legal at compute_103) ----------------
#define LDSM_X4(r, addr) \
    asm volatile("ldmatrix.sync.aligned.m8n8.x4.shared.b16 {%0,%1,%2,%3}, [%4];" \
                 : "=r"((r)[0]), "=r"((r)[1]), "=r"((r)[2]), "=r"((r)[3]) : "r"(addr))
#define LDSM_X4T(r, addr) \
    asm volatile("ldmatrix.sync.aligned.m8n8.x4.trans.shared.b16 {%0,%1,%2,%3}, [%4];" \
                 : "=r"((r)[0]), "=r"((r)[1]), "=r"((r)[2]), "=r"((r)[3]) : "r"(addr))
#define LDSM_X2T(r0, r1, addr) \
    asm volatile("ldmatrix.sync.aligned.m8n8.x2.trans.shared.b16 {%0,%1}, [%2];" \
                 : "=r"(r0), "=r"(r1) : "r"(addr))
#define MMA16816(c, a, b0, b1) \
    asm volatile("mma.sync.aligned.m16n8k16.row.col.f32.f16.f16.f32 " \
                 "{%0,%1,%2,%3}, {%4,%5,%6,%7}, {%8,%9}, {%0,%1,%2,%3};" \
                 : "+f"((c)[0]), "+f"((c)[1]), "+f"((c)[2]), "+f"((c)[3]) \
                 : "r"((a)[0]), "r"((a)[1]), "r"((a)[2]), "r"((a)[3]), "r"(b0), "r"(b1))

// ---------------- launch 0: user gather + movie projection + degree count ----------------
__global__ __launch_bounds__(256) void k_prep(
    const int* uw, const void* unid, const void* mnid,
    const float* ue, const float* mx, const float* W, const float* bb,
    const float* memb, const void* es, const void* ed,
    int U, int M, int F, int E, int GG, int GM, int GC) {
    __shared__ float2 sW[32 * 32];
    int f64 = detect64(uw);
    if ((int)blockIdx.x < GG) {
        // x_user(f16) = user_emb[user_node_id]; thread = 8 floats -> 1 uint4 store
        int j = blockIdx.x * 256 + threadIdx.x;
        if (j < U * 8) {
            int node = j >> 3, q8 = j & 7;
            int uid = ldidx(unid, node, f64);
            const float4* base = reinterpret_cast<const float4*>(ue) + (size_t)uid * 16;
            uint2 lo = f4_to_h4(base[2 * q8]);
            uint2 hi = f4_to_h4(base[2 * q8 + 1]);
            uint4 pkt;
            pkt.x = lo.x; pkt.y = lo.y; pkt.z = hi.x; pkt.w = hi.y;
            d_x16_u[(size_t)node * 8 + q8] = pkt;
        }
    } else if ((int)blockIdx.x < GG + GM) {
        // x_movie(f16) = movie_x @ w_movie + b + movie_emb[id]
        for (int idx = threadIdx.x; idx < F * 32; idx += 256) {
            int f = idx >> 5, t = idx & 31;
            sW[idx] = make_float2(W[f * HD + t], W[f * HD + t + 32]);
        }
        __syncthreads();
        int lane = threadIdx.x & 31, warp = threadIdx.x >> 5;
        int mb = blockIdx.x - GG;
        __half* xm16 = reinterpret_cast<__half*>(d_x16_m);
        for (int m = mb * 8 + warp; m < M; m += GM * 8) {
            float mxv = (lane < F) ? mx[(size_t)m * F + lane] : 0.f;
            int mid = ldidx(mnid, m, f64);
            float acc0 = bb[lane] + memb[(size_t)mid * HD + lane];
            float acc1 = bb[lane + 32] + memb[(size_t)mid * HD + lane + 32];
            for (int f = 0; f < F; f++) {
                float v = __shfl_sync(0xffffffffu, mxv, f);
                float2 wv = sW[f * 32 + lane];
                acc0 += v * wv.x;
                acc1 += v * wv.y;
            }
            xm16[(size_t)m * HD + lane] = __float2half_rn(acc0);
            xm16[(size_t)m * HD + lane + 32] = __float2half_rn(acc1);
        }
    } else {
        int cb = blockIdx.x - (GG + GM);
        for (int e = cb * 256 + threadIdx.x; e < E; e += GC * 256) {
            atomicAdd(&d_deg[ldidx(es, e, f64)], 1);
            atomicAdd(&d_deg[U + ldidx(ed, e, f64)], 1);
        }
    }
}

// ---------------- launch 1: decoupled-lookback scan over combined deg ----------------
__global__ __launch_bounds__(1024) void k_scan_lb(int U, int M, int E) {
    __shared__ int sh[1024];
    __shared__ int sRun;
    int n = U + M;
    int tid = threadIdx.x, bid = blockIdx.x;
    int base = bid * 4096 + tid * 4;
    int4 v = make_int4(0, 0, 0, 0);
    if (base + 3 < n)
        v = *reinterpret_cast<const int4*>(d_deg + base);
    else {
        if (base < n) v.x = d_deg[base];
        if (base + 1 < n) v.y = d_deg[base + 1];
        if (base + 2 < n) v.z = d_deg[base + 2];
    }
    int loc = v.x + v.y + v.z + v.w;
    sh[tid] = loc;
    __syncthreads();
    for (int o = 1; o < 1024; o <<= 1) {
        int a = (tid >= o) ? sh[tid - o] : 0;
        __syncthreads();
        sh[tid] += a;
        __syncthreads();
    }
    int incl = sh[tid];
    int bsum = sh[1023];
    if (tid == 0) {
        int run = 0;
        if (bid == 0) {
            d_lb_inc[0] = bsum;
            __threadfence();
            d_lb_flag[0] = 2;
        } else {
            d_lb_agg[bid] = bsum;
            __threadfence();
            d_lb_flag[bid] = 1;
            int p = bid - 1;
            while (true) {
                int f;
                while ((f = d_lb_flag[p]) == 0) {}
                __threadfence();
                if (f == 2) { run += d_lb_inc[p]; break; }
                run += d_lb_agg[p];
                p--;
            }
            d_lb_inc[bid] = run + bsum;
            __threadfence();
            d_lb_flag[bid] = 2;
        }
        sRun = run;
    }
    __syncthreads();
    int e = sRun + incl - loc;
    int vv[4] = {v.x, v.y, v.z, v.w};
#pragma unroll
    for (int w = 0; w < 4; w++) {
        int gi = base + w;
        if (gi < n) {
            if (gi < U) { d_off_u[gi] = e; d_cur_u[gi] = e; }
            else { d_off_m[gi - U] = e - E; d_cur_m[gi - U] = e - E; }
        }
        e += vv[w];
    }
    if (bid == 0 && tid == 0) { d_off_u[U] = E; d_off_m[M] = E; }
}

// ---------------- launch 2: fill adjacency ----------------
__global__ void k_fill(const int* uw, const void* es, const void* ed, int n) {
    int f64 = detect64(uw);
    for (int e = blockIdx.x * blockDim.x + threadIdx.x; e < n;
         e += gridDim.x * blockDim.x) {
        int s = ldidx(es, e, f64);
        int d = ldidx(ed, e, f64);
        d_nbr_u[atomicAdd(&d_cur_u[s], 1)] = d;
        d_nbr_m[atomicAdd(&d_cur_m[d], 1)] = s;
    }
}

// ---------------- gather: f16 src rows, quad-wise HADD2 + fp32 accumulate, f16 store ----------------
__global__ __launch_bounds__(256) void k_gather(const uint2* __restrict__ src,
                                                uint2* __restrict__ dst,
                                                const int* __restrict__ off,
                                                const int* __restrict__ nbr,
                                                int n_dst) {
    int lane = threadIdx.x & 31, warp = threadIdx.x >> 5;
    int half = lane >> 4, l16 = lane & 15;
    for (int i = blockIdx.x * 8 + warp; i < n_dst; i += gridDim.x * 8) {
        int s0 = off[i], s1 = off[i + 1];
        float4 acc = make_float4(0.f, 0.f, 0.f, 0.f);
        for (int j = s0; j < s1; j += 32) {
            int myn = (j + lane < s1) ? nbr[j + lane] : 0;
            int cnt = min(32, s1 - j);
            int jj = 0;
            for (; jj + 8 <= cnt; jj += 8) {
                int n0 = __shfl_sync(0xffffffffu, myn, jj + half);
                int n1 = __shfl_sync(0xffffffffu, myn, jj + 2 + half);
                int n2 = __shfl_sync(0xffffffffu, myn, jj + 4 + half);
                int n3 = __shfl_sync(0xffffffffu, myn, jj + 6 + half);
                uint2 v0 = src[(size_t)n0 * 16 + l16];
                uint2 v1 = src[(size_t)n1 * 16 + l16];
                uint2 v2 = src[(size_t)n2 * 16 + l16];
                uint2 v3 = src[(size_t)n3 * 16 + l16];
                // quad-wise f16 partial sum (6 HADD2), single convert to fp32
                __half2 slo = __hadd2(__hadd2(u2h(v0.x), u2h(v1.x)),
                                      __hadd2(u2h(v2.x), u2h(v3.x)));
                __half2 shi = __hadd2(__hadd2(u2h(v0.y), u2h(v1.y)),
                                      __hadd2(u2h(v2.y), u2h(v3.y)));
                float2 flo = __half22float2(slo);
                float2 fhi = __half22float2(shi);
                acc.x += flo.x; acc.y += flo.y; acc.z += fhi.x; acc.w += fhi.y;
            }
            for (; jj + 2 <= cnt; jj += 2) {
                int nn = __shfl_sync(0xffffffffu, myn, jj + half);
                acc_h4(acc, src[(size_t)nn * 16 + l16]);
            }
            if (jj < cnt) {
                int nn = __shfl_sync(0xffffffffu, myn, cnt - 1);
                if (half == 0) acc_h4(acc, src[(size_t)nn * 16 + l16]);
            }
        }
        acc.x += __shfl_xor_sync(0xffffffffu, acc.x, 16);
        acc.y += __shfl_xor_sync(0xffffffffu, acc.y, 16);
        acc.z += __shfl_xor_sync(0xffffffffu, acc.z, 16);
        acc.w += __shfl_xor_sync(0xffffffffu, acc.w, 16);
        if (half == 0) {
            float inv = 1.f / (float)max(s1 - s0, 1);
            dst[(size_t)i * 16 + l16] = f4_to_h4(
                make_float4(acc.x * inv, acc.y * inv, acc.z * inv, acc.w * inv));
        }
    }
}

// ---------------- mma.sync xform: out = [agg16|xd16][128 x 128k] @ [Wl;Wr][128 x 64] + b ----------------
#define XF_SA 0
#define XF_SB 34816                  /* 128 * 272 */
#define XF_BIAS (XF_SB + 18432)      /* 128 * 144 */
#define XF_SMEM (XF_BIAS + 256)
__global__ __launch_bounds__(128) void k_xform_mma(
    const uint4* __restrict__ agg16U, const uint4* __restrict__ xd16U,
    const uint4* __restrict__ agg16M, const uint4* __restrict__ xd16M,
    const float* __restrict__ WlU, const float* __restrict__ WrU,
    const float* __restrict__ blU,
    const float* __restrict__ WlM, const float* __restrict__ WrM,
    const float* __restrict__ blM,
    __half* __restrict__ out16U, __half* __restrict__ out16M,
    int NU, int NM, int XU, int doRelu) {
    extern __shared__ char smem[];
    int t = threadIdx.x;
    int lane = t & 31, w = t >> 5;

    int segU = (int)blockIdx.x < XU;
    const uint4* agg = segU ? agg16U : agg16M;
    const uint4* xd = segU ? xd16U : xd16M;
    const float* Wl = segU ? WlU : WlM;
    const float* Wr = segU ? WrU : WrM;
    const float* bl = segU ? blU : blM;
    __half* out16 = segU ? out16U : out16M;
    int N = segU ? NU : NM;
    int n0 = (segU ? blockIdx.x : blockIdx.x - XU) * 128;

    // stage A: node n0+t -> sA row t ([agg 64 | xd 64] halves), stride 272B
    {
        const uint4* ar = agg + (size_t)(n0 + t) * 8;
        const uint4* xr = xd + (size_t)(n0 + t) * 8;
        uint4* rowA = reinterpret_cast<uint4*>(smem + XF_SA + t * 272);
#pragma unroll
        for (int q = 0; q < 8; q++) rowA[q] = ar[q];
#pragma unroll
        for (int q = 0; q < 8; q++) rowA[8 + q] = xr[q];
    }
    // stage B: k row t -> sB[t][n] = (t<64 ? Wl[t][n] : Wr[t-64][n]) f16, stride 144B
    {
        const float* Wg = (t < 64) ? (Wl + t * HD) : (Wr + (t - 64) * HD);
        uint4* rowB = reinterpret_cast<uint4*>(smem + XF_SB + t * 144);
#pragma unroll
        for (int q = 0; q < 8; q++) {
            float4 w0 = reinterpret_cast<const float4*>(Wg)[2 * q];
            float4 w1 = reinterpret_cast<const float4*>(Wg)[2 * q + 1];
            uint2 lo = f4_to_h4(w0), hi = f4_to_h4(w1);
            uint4 pkt;
            pkt.x = lo.x; pkt.y = lo.y; pkt.z = hi.x; pkt.w = hi.y;
            rowB[q] = pkt;
        }
    }
    float* sbias = reinterpret_cast<float*>(smem + XF_BIAS);
    if (t < 64) sbias[t] = bl[t];
    __syncthreads();

    uint32_t smem32 = smem_u32(smem);
    float acc[2][8][4];
#pragma unroll
    for (int mt = 0; mt < 2; mt++)
#pragma unroll
        for (int nt = 0; nt < 8; nt++)
#pragma unroll
            for (int c = 0; c < 4; c++) acc[mt][nt][c] = 0.f;

    uint32_t aAddr0, aAddr1, bAddr;
    {
        int r = lane & 15;
        int cb = (lane >> 4) * 16;
        aAddr0 = smem32 + XF_SA + (uint32_t)(w * 32 + r) * 272 + cb;
        aAddr1 = aAddr0 + 16 * 272;
        int quad = lane >> 3, i = lane & 7;
        int row = (quad & 1) * 8 + i;
        int colb = (quad >> 1) * 16;
        bAddr = smem32 + XF_SB + (uint32_t)row * 144 + colb;
    }

#pragma unroll
    for (int kk = 0; kk < 8; kk++) {
        uint32_t a0[4], a1[4];
        LDSM_X4(a0, aAddr0 + kk * 32);
        LDSM_X4(a1, aAddr1 + kk * 32);
#pragma unroll
        for (int nt2 = 0; nt2 < 4; nt2++) {
            uint32_t b[4];
            LDSM_X4T(b, bAddr + kk * 2304 + nt2 * 32);
            MMA16816(acc[0][2 * nt2], a0, b[0], b[1]);
            MMA16816(acc[0][2 * nt2 + 1], a0, b[2], b[3]);
            MMA16816(acc[1][2 * nt2], a1, b[0], b[1]);
            MMA16816(acc[1][2 * nt2 + 1], a1, b[2], b[3]);
        }
    }

    // epilogue: fragment layout m16n8 -> rows g,g+8, cols 2*q4,+1
    int g = lane >> 2, q4 = lane & 3;
#pragma unroll
    for (int mt = 0; mt < 2; mt++) {
        int r0 = n0 + w * 32 + mt * 16 + g;
        int r1 = r0 + 8;
#pragma unroll
        for (int nt = 0; nt < 8; nt++) {
            int col = nt * 8 + q4 * 2;
            float b0 = sbias[col], b1 = sbias[col + 1];
            float o00 = acc[mt][nt][0] + b0, o01 = acc[mt][nt][1] + b1;
            float o10 = acc[mt][nt][2] + b0, o11 = acc[mt][nt][3] + b1;
            if (doRelu) {
                o00 = fmaxf(o00, 0.f); o01 = fmaxf(o01, 0.f);
                o10 = fmaxf(o10, 0.f); o11 = fmaxf(o11, 0.f);
            }
            if (r0 < N) {
                __half2 h = __floats2half2_rn(o00, o01);
                *reinterpret_cast<__half2*>(out16 + (size_t)r0 * HD + col) = h;
            }
            if (r1 < N) {
                __half2 h = __floats2half2_rn(o10, o11);
                *reinterpret_cast<__half2*>(out16 + (size_t)r1 * HD + col) = h;
            }
        }
    }
}

// ---------------- final: mma edge classifier (warp-per-16-edges) + scratch re-zero ----------------
#define CLS_WARPS 4
__global__ __launch_bounds__(128) void k_classify_mma(
    const int* uw, const void* els, const void* eld,
    const float* __restrict__ W, const float* __restrict__ b,
    const uint4* __restrict__ u2h, const uint4* __restrict__ m2h,
    float* __restrict__ out, int EL, int GZ, int GC) {
    if ((int)blockIdx.x < GZ) {
        int i = blockIdx.x * 128 + threadIdx.x;
        if (i < NTOT) d_deg[i] = 0;
        else if (i < NTOT + 512) d_lb_flag[i - NTOT] = 0;
        return;
    }
    __shared__ __align__(16) char sA[CLS_WARPS][16 * 272];  // 17408B
    __shared__ __align__(16) __half sB[128 * 8];            // [k][8] (7 used)
    __shared__ float sbias[8];
    int t = threadIdx.x, lane = t & 31, w = t >> 5;

    // stage B (cls_W f16, padded to 8 cols) + bias
    {
        const float* wr = W + t * CN;
        __half h[8];
#pragma unroll
        for (int c = 0; c < CN; c++) h[c] = __float2half_rn(wr[c]);
        h[7] = __float2half_rn(0.f);
        *reinterpret_cast<uint4*>(&sB[t * 8]) = *reinterpret_cast<uint4*>(h);
    }
    if (t < 8) sbias[t] = (t < CN) ? b[t] : 0.f;
    __syncthreads();

    // hoist B fragments (8 k-steps x 2 regs), reused for every edge tile
    uint32_t smemB = smem_u32(sB);
    uint32_t bf0[8], bf1[8];
#pragma unroll
    for (int kk = 0; kk < 8; kk++)
        LDSM_X2T(bf0[kk], bf1[kk], smemB + (uint32_t)(kk * 16 + (lane & 15)) * 16);

    int f64 = detect64(uw);
    uint32_t sAbase = smem_u32(&sA[w][0]);
    int quarter = lane >> 3, chunk = lane & 7;
    int g = lane >> 2, q4 = lane & 3, col = 2 * q4;
    float b0 = sbias[col], b1 = sbias[col < 6 ? col + 1 : 7];
    uint32_t a0base = sAbase + (uint32_t)(lane & 15) * 272 + (uint32_t)(lane >> 4) * 16;

    int ntile = (EL + 15) >> 4;
    int cb = blockIdx.x - GZ;
    for (int tile = cb * CLS_WARPS + w; tile < ntile; tile += GC * CLS_WARPS) {
        int tbase = tile << 4;
        int ge = tbase + lane;
        int sI = 0, dI = 0;
        if (lane < 16 && ge < EL) {
            sI = ldidx(els, ge, f64);
            dI = ldidx(eld, ge, f64);
        }
        // stage A: 4 reps x 4 edges; 8 lanes per edge load u-row + m-row (128B each)
#pragma unroll
        for (int rep = 0; rep < 4; rep++) {
            int ei = rep * 4 + quarter;
            int s = __shfl_sync(0xffffffffu, sI, ei);
            int d = __shfl_sync(0xffffffffu, dI, ei);
            uint4 uv = u2h[(size_t)s * 8 + chunk];
            uint4 mv = m2h[(size_t)d * 8 + chunk];
            *reinterpret_cast<uint4*>(&sA[w][ei * 272 + chunk * 16]) = uv;
            *reinterpret_cast<uint4*>(&sA[w][ei * 272 + 128 + chunk * 16]) = mv;
        }
        __syncwarp();

        float acc[4] = {0.f, 0.f, 0.f, 0.f};
#pragma unroll
        for (int kk = 0; kk < 8; kk++) {
            uint32_t a0[4];
            LDSM_X4(a0, a0base + kk * 32);
            MMA16816(acc, a0, bf0[kk], bf1[kk]);
        }
        __syncwarp();

        // epilogue: rows g, g+8 of the m16 tile = edges; cols 2q4, 2q4+1
        int e0 = tbase + g;
        int e1 = e0 + 8;
        float o00 = acc[0] + b0, o01 = acc[1] + b1;
        float o10 = acc[2] + b0, o11 = acc[3] + b1;
        if (e0 < EL) {
            out[(size_t)e0 * CN + col] = o00;
            if (col < 6) out[(size_t)e0 * CN + col + 1] = o01;
        }
        if (e1 < EL) {
            out[(size_t)e1 * CN + col] = o10;
            if (col < 6) out[(size_t)e1 * CN + col + 1] = o11;
        }
    }
}

// ---------------- host launch ----------------
extern "C" void kernel_launch(void* const* d_in, const int* in_sizes, int n_in,
                              void* d_out, int out_size) {
    const int* uw = (const int*)d_in[0];
    const void* unid = d_in[0];
    const void* mnid = d_in[1];
    const float* movie_x = (const float*)d_in[2];
    const void* esrc = d_in[3];
    const void* edst = d_in[4];
    const void* elsrc = d_in[5];
    const void* eldst = d_in[6];
    const float* user_emb = (const float*)d_in[7];
    const float* movie_emb = (const float*)d_in[8];
    const float* w_movie = (const float*)d_in[9];
    const float* b_movie = (const float*)d_in[10];

    int U = in_sizes[0];
    int M = in_sizes[1];
    int E = in_sizes[3];
    int EL = in_sizes[5];
    int F = in_sizes[2] / M;
    (void)n_in; (void)out_size;

    void *p_off_u, *p_off_m, *p_nbr_u, *p_nbr_m;
    void *p_x16u, *p_x16m, *p_agg16u, *p_agg16m, *p_h1u, *p_h1m, *p_u2h, *p_m2h;
    cudaGetSymbolAddress(&p_off_u, d_off_u);
    cudaGetSymbolAddress(&p_off_m, d_off_m);
    cudaGetSymbolAddress(&p_nbr_u, d_nbr_u);
    cudaGetSymbolAddress(&p_nbr_m, d_nbr_m);
    cudaGetSymbolAddress(&p_x16u, d_x16_u);
    cudaGetSymbolAddress(&p_x16m, d_x16_m);
    cudaGetSymbolAddress(&p_agg16u, d_agg16_u);
    cudaGetSymbolAddress(&p_agg16m, d_agg16_m);
    cudaGetSymbolAddress(&p_h1u, d_h1_u);
    cudaGetSymbolAddress(&p_h1m, d_h1_m);
    cudaGetSymbolAddress(&p_u2h, d_u2h);
    cudaGetSymbolAddress(&p_m2h, d_m2h);

    cudaFuncSetAttribute(k_xform_mma, cudaFuncAttributeMaxDynamicSharedMemorySize,
                         XF_SMEM);

    const int* off_u = (const int*)p_off_u;
    const int* off_m = (const int*)p_off_m;
    const int* nbr_u = (const int*)p_nbr_u;
    const int* nbr_m = (const int*)p_nbr_m;

    // 0: prep (f16 x_user / x_movie + degree count)
    int GG = (U * 8 + 255) / 256;
    int GM = 1024;
    int GC = 2048;
    k_prep<<<GG + GM + GC, 256>>>(uw, unid, mnid, user_emb, movie_x, w_movie,
                                  b_movie, movie_emb, esrc, edst,
                                  U, M, F, E, GG, GM, GC);
    // 1: scan (decoupled lookback)
    int NB = (U + M + 4095) / 4096;
    k_scan_lb<<<NB, 1024>>>(U, M, E);
    // 2: fill
    k_fill<<<2048, 256>>>(uw, esrc, edst, E);

    const int GB = 1776;
    int XU = (U + 127) / 128, XM = (M + 127) / 128;

    // 3: gather layer1 U (agg16_u <- x16_m)  [ncu target]
    k_gather<<<GB, 256>>>((const uint2*)p_x16m, (uint2*)p_agg16u, off_u, nbr_u, U);
    // 4: gather layer1 M (agg16_m <- x16_u)
    k_gather<<<GB, 256>>>((const uint2*)p_x16u, (uint2*)p_agg16m, off_m, nbr_m, M);
    // 5: mma xform layer1 (relu) -> h1 f16
    k_xform_mma<<<XU + XM, 128, XF_SMEM>>>(
        (const uint4*)p_agg16u, (const uint4*)p_x16u,
        (const uint4*)p_agg16m, (const uint4*)p_x16m,
        (const float*)d_in[14], (const float*)d_in[16], (const float*)d_in[15],
        (const float*)d_in[11], (const float*)d_in[13], (const float*)d_in[12],
        (__half*)p_h1u, (__half*)p_h1m, U, M, XU, 1);
    // 6: gather layer2 U (agg16_u <- h1_m)
    k_gather<<<GB, 256>>>((const uint2*)p_h1m, (uint2*)p_agg16u, off_u, nbr_u, U);
    // 7: gather layer2 M (agg16_m <- h1_u)
    k_gather<<<GB, 256>>>((const uint2*)p_h1u, (uint2*)p_agg16m, off_m, nbr_m, M);
    // 8: mma xform layer2 (no relu) -> u2h/m2h f16
    k_xform_mma<<<XU + XM, 128, XF_SMEM>>>(
        (const uint4*)p_agg16u, (const uint4*)p_h1u,
        (const uint4*)p_agg16m, (const uint4*)p_h1m,
        (const float*)d_in[20], (const float*)d_in[22], (const float*)d_in[21],
        (const float*)d_in[17], (const float*)d_in[19], (const float*)d_in[18],
        (__half*)p_u2h, (__half*)p_m2h, U, M, XU, 0);
    // 9: mma classifier + scratch re-zero
    int GZ = (NTOT + 512 + 127) / 128;
    int GCC = 1480;
    k_classify_mma<<<GZ + GCC, 128>>>(uw, elsrc, eldst, (const float*)d_in[23],
                                      (const float*)d_in[24],
                                      (const uint4*)p_u2h, (const uint4*)p_m2h,
                                      (float*)d_out, EL, GZ, GCC);
}

// round 17
// speedup vs baseline: 1.0433x; 1.0120x over previous
#include <cuda_runtime.h>
#include <cuda_fp16.h>
#include <cstdint>

#define U_N 200000
#define M_N 100000
#define E_N 2000000
#define HD 64
#define CN 7
#define NTOT (U_N + M_N)

// ---------------- device scratch (static; zero-initialized at module load) ----------------
// d_deg and d_lb_flag are re-zeroed at the END of every kernel_launch (tail
// blocks of the classifier), so every graph replay starts from a clean state.
__device__ int d_deg[NTOT];
__device__ int d_off_u[U_N + 1];
__device__ int d_off_m[M_N + 1];
__device__ int d_cur_u[U_N];
__device__ int d_cur_m[M_N];
__device__ int d_nbr_u[E_N];
__device__ int d_nbr_m[E_N];
__device__ volatile int d_lb_flag[512];
__device__ int d_lb_agg[512];
__device__ int d_lb_inc[512];
// f16 feature buffers: [N][64] halves = uint4[N][8]; +128 rows pad for MMA tile tails
__device__ uint4 d_x16_u[(size_t)(U_N + 128) * 8];
__device__ uint4 d_x16_m[(size_t)(M_N + 128) * 8];
__device__ uint4 d_agg16_u[(size_t)(U_N + 128) * 8];
__device__ uint4 d_agg16_m[(size_t)(M_N + 128) * 8];
__device__ uint4 d_h1_u[(size_t)(U_N + 128) * 8];
__device__ uint4 d_h1_m[(size_t)(M_N + 128) * 8];
// f16 final layer-2 outputs (classifier inputs)
__device__ uint4 d_u2h[(size_t)U_N * 8];
__device__ uint4 d_m2h[(size_t)M_N * 8];

// ---------------- generic helpers ----------------
__device__ __forceinline__ int ldidx(const void* p, int i, int f64) {
    return f64 ? (int)((const long long*)p)[i] : ((const int*)p)[i];
}
__device__ __forceinline__ int detect64(const int* uw) { return uw[3] == 0; }
__device__ __forceinline__ uint2 f4_to_h4(float4 v) {
    __half2 a = __floats2half2_rn(v.x, v.y);
    __half2 b = __floats2half2_rn(v.z, v.w);
    uint2 r;
    r.x = *reinterpret_cast<unsigned int*>(&a);
    r.y = *reinterpret_cast<unsigned int*>(&b);
    return r;
}
__device__ __forceinline__ __half2 u2h(unsigned int x) {
    return *reinterpret_cast<__half2*>(&x);
}
__device__ __forceinline__ void acc_h4(float4& acc, uint2 raw) {
    float2 fa = __half22float2(u2h(raw.x)), fb = __half22float2(u2h(raw.y));
    acc.x += fa.x; acc.y += fa.y; acc.z += fb.x; acc.w += fb.y;
}
__device__ __forceinline__ uint32_t smem_u32(const void* p) {
    uint32_t a;
    asm("{ .reg .u64 t; cvta.to.shared.u64 t, %1; cvt.u32.u64 %0, t; }" : "=r"(a) : "l"(p));
    return a;
}

// ---------------- mma.sync helpers (baseline PTX, sm_80+: legal at compute_103) ----------------
#define LDSM_X4(r, addr) \
    asm volatile("ldmatrix.sync.aligned.m8n8.x4.shared.b16 {%0,%1,%2,%3}, [%4];" \
                 : "=r"((r)[0]), "=r"((r)[1]), "=r"((r)[2]), "=r"((r)[3]) : "r"(addr))
#define LDSM_X4T(r, addr) \
    asm volatile("ldmatrix.sync.aligned.m8n8.x4.trans.shared.b16 {%0,%1,%2,%3}, [%4];" \
                 : "=r"((r)[0]), "=r"((r)[1]), "=r"((r)[2]), "=r"((r)[3]) : "r"(addr))
#define LDSM_X2T(r0, r1, addr) \
    asm volatile("ldmatrix.sync.aligned.m8n8.x2.trans.shared.b16 {%0,%1}, [%2];" \
                 : "=r"(r0), "=r"(r1) : "r"(addr))
#define MMA16816(c, a, b0, b1) \
    asm volatile("mma.sync.aligned.m16n8k16.row.col.f32.f16.f16.f32 " \
                 "{%0,%1,%2,%3}, {%4,%5,%6,%7}, {%8,%9}, {%0,%1,%2,%3};" \
                 : "+f"((c)[0]), "+f"((c)[1]), "+f"((c)[2]), "+f"((c)[3]) \
                 : "r"((a)[0]), "r"((a)[1]), "r"((a)[2]), "r"((a)[3]), "r"(b0), "r"(b1))

// ---------------- feature prep: x_user gather + x_movie projection (f16) ----------------
__global__ __launch_bounds__(256) void k_feat(
    const int* uw, const void* unid, const void* mnid,
    const float* ue, const float* mx, const float* W, const float* bb,
    const float* memb, int U, int M, int F, int GG, int GM) {
    __shared__ float2 sW[32 * 32];
    int f64 = detect64(uw);
    if ((int)blockIdx.x < GG) {
        // x_user(f16) = user_emb[user_node_id]; thread = 8 floats -> 1 uint4 store
        int j = blockIdx.x * 256 + threadIdx.x;
        if (j < U * 8) {
            int node = j >> 3, q8 = j & 7;
            int uid = ldidx(unid, node, f64);
            const float4* base = reinterpret_cast<const float4*>(ue) + (size_t)uid * 16;
            uint2 lo = f4_to_h4(base[2 * q8]);
            uint2 hi = f4_to_h4(base[2 * q8 + 1]);
            uint4 pkt;
            pkt.x = lo.x; pkt.y = lo.y; pkt.z = hi.x; pkt.w = hi.y;
            d_x16_u[(size_t)node * 8 + q8] = pkt;
        }
    } else {
        // x_movie(f16) = movie_x @ w_movie + b + movie_emb[id]
        for (int idx = threadIdx.x; idx < F * 32; idx += 256) {
            int f = idx >> 5, t = idx & 31;
            sW[idx] = make_float2(W[f * HD + t], W[f * HD + t + 32]);
        }
        __syncthreads();
        int lane = threadIdx.x & 31, warp = threadIdx.x >> 5;
        int mb = blockIdx.x - GG;
        __half* xm16 = reinterpret_cast<__half*>(d_x16_m);
        for (int m = mb * 8 + warp; m < M; m += GM * 8) {
            float mxv = (lane < F) ? mx[(size_t)m * F + lane] : 0.f;
            int mid = ldidx(mnid, m, f64);
            float acc0 = bb[lane] + memb[(size_t)mid * HD + lane];
            float acc1 = bb[lane + 32] + memb[(size_t)mid * HD + lane + 32];
            for (int f = 0; f < F; f++) {
                float v = __shfl_sync(0xffffffffu, mxv, f);
                float2 wv = sW[f * 32 + lane];
                acc0 += v * wv.x;
                acc1 += v * wv.y;
            }
            xm16[(size_t)m * HD + lane] = __float2half_rn(acc0);
            xm16[(size_t)m * HD + lane + 32] = __float2half_rn(acc1);
        }
    }
}

// ---------------- degree count ----------------
__global__ void k_count(const int* uw, const void* es, const void* ed, int U, int E) {
    int f64 = detect64(uw);
    for (int e = blockIdx.x * blockDim.x + threadIdx.x; e < E;
         e += gridDim.x * blockDim.x) {
        atomicAdd(&d_deg[ldidx(es, e, f64)], 1);
        atomicAdd(&d_deg[U + ldidx(ed, e, f64)], 1);
    }
}

// ---------------- decoupled-lookback scan over combined deg ----------------
__global__ __launch_bounds__(1024) void k_scan_lb(int U, int M, int E) {
    __shared__ int sh[1024];
    __shared__ int sRun;
    int n = U + M;
    int tid = threadIdx.x, bid = blockIdx.x;
    int base = bid * 4096 + tid * 4;
    int4 v = make_int4(0, 0, 0, 0);
    if (base + 3 < n)
        v = *reinterpret_cast<const int4*>(d_deg + base);
    else {
        if (base < n) v.x = d_deg[base];
        if (base + 1 < n) v.y = d_deg[base + 1];
        if (base + 2 < n) v.z = d_deg[base + 2];
    }
    int loc = v.x + v.y + v.z + v.w;
    sh[tid] = loc;
    __syncthreads();
    for (int o = 1; o < 1024; o <<= 1) {
        int a = (tid >= o) ? sh[tid - o] : 0;
        __syncthreads();
        sh[tid] += a;
        __syncthreads();
    }
    int incl = sh[tid];
    int bsum = sh[1023];
    if (tid == 0) {
        int run = 0;
        if (bid == 0) {
            d_lb_inc[0] = bsum;
            __threadfence();
            d_lb_flag[0] = 2;
        } else {
            d_lb_agg[bid] = bsum;
            __threadfence();
            d_lb_flag[bid] = 1;
            int p = bid - 1;
            while (true) {
                int f;
                while ((f = d_lb_flag[p]) == 0) {}
                __threadfence();
                if (f == 2) { run += d_lb_inc[p]; break; }
                run += d_lb_agg[p];
                p--;
            }
            d_lb_inc[bid] = run + bsum;
            __threadfence();
            d_lb_flag[bid] = 2;
        }
        sRun = run;
    }
    __syncthreads();
    int e = sRun + incl - loc;
    int vv[4] = {v.x, v.y, v.z, v.w};
#pragma unroll
    for (int w = 0; w < 4; w++) {
        int gi = base + w;
        if (gi < n) {
            if (gi < U) { d_off_u[gi] = e; d_cur_u[gi] = e; }
            else { d_off_m[gi - U] = e - E; d_cur_m[gi - U] = e - E; }
        }
        e += vv[w];
    }
    if (bid == 0 && tid == 0) { d_off_u[U] = E; d_off_m[M] = E; }
}

// ---------------- fill adjacency ----------------
__global__ void k_fill(const int* uw, const void* es, const void* ed, int n) {
    int f64 = detect64(uw);
    for (int e = blockIdx.x * blockDim.x + threadIdx.x; e < n;
         e += gridDim.x * blockDim.x) {
        int s = ldidx(es, e, f64);
        int d = ldidx(ed, e, f64);
        d_nbr_u[atomicAdd(&d_cur_u[s], 1)] = d;
        d_nbr_m[atomicAdd(&d_cur_m[d], 1)] = s;
    }
}

// ---------------- gather: f16 src rows, quad-wise HADD2 + fp32 accumulate, f16 store ----------------
__global__ __launch_bounds__(256) void k_gather(const uint2* __restrict__ src,
                                                uint2* __restrict__ dst,
                                                const int* __restrict__ off,
                                                const int* __restrict__ nbr,
                                                int n_dst) {
    int lane = threadIdx.x & 31, warp = threadIdx.x >> 5;
    int half = lane >> 4, l16 = lane & 15;
    for (int i = blockIdx.x * 8 + warp; i < n_dst; i += gridDim.x * 8) {
        int s0 = off[i], s1 = off[i + 1];
        float4 acc = make_float4(0.f, 0.f, 0.f, 0.f);
        for (int j = s0; j < s1; j += 32) {
            int myn = (j + lane < s1) ? nbr[j + lane] : 0;
            int cnt = min(32, s1 - j);
            int jj = 0;
            for (; jj + 8 <= cnt; jj += 8) {
                int n0 = __shfl_sync(0xffffffffu, myn, jj + half);
                int n1 = __shfl_sync(0xffffffffu, myn, jj + 2 + half);
                int n2 = __shfl_sync(0xffffffffu, myn, jj + 4 + half);
                int n3 = __shfl_sync(0xffffffffu, myn, jj + 6 + half);
                uint2 v0 = src[(size_t)n0 * 16 + l16];
                uint2 v1 = src[(size_t)n1 * 16 + l16];
                uint2 v2 = src[(size_t)n2 * 16 + l16];
                uint2 v3 = src[(size_t)n3 * 16 + l16];
                // quad-wise f16 partial sum (6 HADD2), single convert to fp32
                __half2 slo = __hadd2(__hadd2(u2h(v0.x), u2h(v1.x)),
                                      __hadd2(u2h(v2.x), u2h(v3.x)));
                __half2 shi = __hadd2(__hadd2(u2h(v0.y), u2h(v1.y)),
                                      __hadd2(u2h(v2.y), u2h(v3.y)));
                float2 flo = __half22float2(slo);
                float2 fhi = __half22float2(shi);
                acc.x += flo.x; acc.y += flo.y; acc.z += fhi.x; acc.w += fhi.y;
            }
            for (; jj + 2 <= cnt; jj += 2) {
                int nn = __shfl_sync(0xffffffffu, myn, jj + half);
                acc_h4(acc, src[(size_t)nn * 16 + l16]);
            }
            if (jj < cnt) {
                int nn = __shfl_sync(0xffffffffu, myn, cnt - 1);
                if (half == 0) acc_h4(acc, src[(size_t)nn * 16 + l16]);
            }
        }
        acc.x += __shfl_xor_sync(0xffffffffu, acc.x, 16);
        acc.y += __shfl_xor_sync(0xffffffffu, acc.y, 16);
        acc.z += __shfl_xor_sync(0xffffffffu, acc.z, 16);
        acc.w += __shfl_xor_sync(0xffffffffu, acc.w, 16);
        if (half == 0) {
            float inv = 1.f / (float)max(s1 - s0, 1);
            dst[(size_t)i * 16 + l16] = f4_to_h4(
                make_float4(acc.x * inv, acc.y * inv, acc.z * inv, acc.w * inv));
        }
    }
}

// ---------------- mma.sync xform: out = [agg16|xd16][128 x 128k] @ [Wl;Wr][128 x 64] + b ----------------
#define XF_SA 0
#define XF_SB 34816                  /* 128 * 272 */
#define XF_BIAS (XF_SB + 18432)      /* 128 * 144 */
#define XF_SMEM (XF_BIAS + 256)
__global__ __launch_bounds__(128) void k_xform_mma(
    const uint4* __restrict__ agg16U, const uint4* __restrict__ xd16U,
    const uint4* __restrict__ agg16M, const uint4* __restrict__ xd16M,
    const float* __restrict__ WlU, const float* __restrict__ WrU,
    const float* __restrict__ blU,
    const float* __restrict__ WlM, const float* __restrict__ WrM,
    const float* __restrict__ blM,
    __half* __restrict__ out16U, __half* __restrict__ out16M,
    int NU, int NM, int XU, int doRelu) {
    extern __shared__ char smem[];
    int t = threadIdx.x;
    int lane = t & 31, w = t >> 5;

    int segU = (int)blockIdx.x < XU;
    const uint4* agg = segU ? agg16U : agg16M;
    const uint4* xd = segU ? xd16U : xd16M;
    const float* Wl = segU ? WlU : WlM;
    const float* Wr = segU ? WrU : WrM;
    const float* bl = segU ? blU : blM;
    __half* out16 = segU ? out16U : out16M;
    int N = segU ? NU : NM;
    int n0 = (segU ? blockIdx.x : blockIdx.x - XU) * 128;

    // stage A: node n0+t -> sA row t ([agg 64 | xd 64] halves), stride 272B
    {
        const uint4* ar = agg + (size_t)(n0 + t) * 8;
        const uint4* xr = xd + (size_t)(n0 + t) * 8;
        uint4* rowA = reinterpret_cast<uint4*>(smem + XF_SA + t * 272);
#pragma unroll
        for (int q = 0; q < 8; q++) rowA[q] = ar[q];
#pragma unroll
        for (int q = 0; q < 8; q++) rowA[8 + q] = xr[q];
    }
    // stage B: k row t -> sB[t][n] = (t<64 ? Wl[t][n] : Wr[t-64][n]) f16, stride 144B
    {
        const float* Wg = (t < 64) ? (Wl + t * HD) : (Wr + (t - 64) * HD);
        uint4* rowB = reinterpret_cast<uint4*>(smem + XF_SB + t * 144);
#pragma unroll
        for (int q = 0; q < 8; q++) {
            float4 w0 = reinterpret_cast<const float4*>(Wg)[2 * q];
            float4 w1 = reinterpret_cast<const float4*>(Wg)[2 * q + 1];
            uint2 lo = f4_to_h4(w0), hi = f4_to_h4(w1);
            uint4 pkt;
            pkt.x = lo.x; pkt.y = lo.y; pkt.z = hi.x; pkt.w = hi.y;
            rowB[q] = pkt;
        }
    }
    float* sbias = reinterpret_cast<float*>(smem + XF_BIAS);
    if (t < 64) sbias[t] = bl[t];
    __syncthreads();

    uint32_t smem32 = smem_u32(smem);
    float acc[2][8][4];
#pragma unroll
    for (int mt = 0; mt < 2; mt++)
#pragma unroll
        for (int nt = 0; nt < 8; nt++)
#pragma unroll
            for (int c = 0; c < 4; c++) acc[mt][nt][c] = 0.f;

    uint32_t aAddr0, aAddr1, bAddr;
    {
        int r = lane & 15;
        int cb = (lane >> 4) * 16;
        aAddr0 = smem32 + XF_SA + (uint32_t)(w * 32 + r) * 272 + cb;
        aAddr1 = aAddr0 + 16 * 272;
        int quad = lane >> 3, i = lane & 7;
        int row = (quad & 1) * 8 + i;
        int colb = (quad >> 1) * 16;
        bAddr = smem32 + XF_SB + (uint32_t)row * 144 + colb;
    }

#pragma unroll
    for (int kk = 0; kk < 8; kk++) {
        uint32_t a0[4], a1[4];
        LDSM_X4(a0, aAddr0 + kk * 32);
        LDSM_X4(a1, aAddr1 + kk * 32);
#pragma unroll
        for (int nt2 = 0; nt2 < 4; nt2++) {
            uint32_t b[4];
            LDSM_X4T(b, bAddr + kk * 2304 + nt2 * 32);
            MMA16816(acc[0][2 * nt2], a0, b[0], b[1]);
            MMA16816(acc[0][2 * nt2 + 1], a0, b[2], b[3]);
            MMA16816(acc[1][2 * nt2], a1, b[0], b[1]);
            MMA16816(acc[1][2 * nt2 + 1], a1, b[2], b[3]);
        }
    }

    // epilogue: fragment layout m16n8 -> rows g,g+8, cols 2*q4,+1
    int g = lane >> 2, q4 = lane & 3;
#pragma unroll
    for (int mt = 0; mt < 2; mt++) {
        int r0 = n0 + w * 32 + mt * 16 + g;
        int r1 = r0 + 8;
#pragma unroll
        for (int nt = 0; nt < 8; nt++) {
            int col = nt * 8 + q4 * 2;
            float b0 = sbias[col], b1 = sbias[col + 1];
            float o00 = acc[mt][nt][0] + b0, o01 = acc[mt][nt][1] + b1;
            float o10 = acc[mt][nt][2] + b0, o11 = acc[mt][nt][3] + b1;
            if (doRelu) {
                o00 = fmaxf(o00, 0.f); o01 = fmaxf(o01, 0.f);
                o10 = fmaxf(o10, 0.f); o11 = fmaxf(o11, 0.f);
            }
            if (r0 < N) {
                __half2 h = __floats2half2_rn(o00, o01);
                *reinterpret_cast<__half2*>(out16 + (size_t)r0 * HD + col) = h;
            }
            if (r1 < N) {
                __half2 h = __floats2half2_rn(o10, o11);
                *reinterpret_cast<__half2*>(out16 + (size_t)r1 * HD + col) = h;
            }
        }
    }
}

// ---------------- final: mma edge classifier (warp-per-16-edges) + scratch re-zero ----------------
#define CLS_WARPS 4
__global__ __launch_bounds__(128) void k_classify_mma(
    const int* uw, const void* els, const void* eld,
    const float* __restrict__ W, const float* __restrict__ b,
    const uint4* __restrict__ u2h, const uint4* __restrict__ m2h,
    float* __restrict__ out, int EL, int GZ, int GC) {
    if ((int)blockIdx.x < GZ) {
        int i = blockIdx.x * 128 + threadIdx.x;
        if (i < NTOT) d_deg[i] = 0;
        else if (i < NTOT + 512) d_lb_flag[i - NTOT] = 0;
        return;
    }
    __shared__ __align__(16) char sA[CLS_WARPS][16 * 272];  // 17408B
    __shared__ __align__(16) __half sB[128 * 8];            // [k][8] (7 used)
    __shared__ float sbias[8];
    int t = threadIdx.x, lane = t & 31, w = t >> 5;

    // stage B (cls_W f16, padded to 8 cols) + bias
    {
        const float* wr = W + t * CN;
        __half h[8];
#pragma unroll
        for (int c = 0; c < CN; c++) h[c] = __float2half_rn(wr[c]);
        h[7] = __float2half_rn(0.f);
        *reinterpret_cast<uint4*>(&sB[t * 8]) = *reinterpret_cast<uint4*>(h);
    }
    if (t < 8) sbias[t] = (t < CN) ? b[t] : 0.f;
    __syncthreads();

    // hoist B fragments (8 k-steps x 2 regs), reused for every edge tile
    uint32_t smemB = smem_u32(sB);
    uint32_t bf0[8], bf1[8];
#pragma unroll
    for (int kk = 0; kk < 8; kk++)
        LDSM_X2T(bf0[kk], bf1[kk], smemB + (uint32_t)(kk * 16 + (lane & 15)) * 16);

    int f64 = detect64(uw);
    uint32_t sAbase = smem_u32(&sA[w][0]);
    int quarter = lane >> 3, chunk = lane & 7;
    int g = lane >> 2, q4 = lane & 3, col = 2 * q4;
    float b0 = sbias[col], b1 = sbias[col < 6 ? col + 1 : 7];
    uint32_t a0base = sAbase + (uint32_t)(lane & 15) * 272 + (uint32_t)(lane >> 4) * 16;

    int ntile = (EL + 15) >> 4;
    int cb = blockIdx.x - GZ;
    for (int tile = cb * CLS_WARPS + w; tile < ntile; tile += GC * CLS_WARPS) {
        int tbase = tile << 4;
        int ge = tbase + lane;
        int sI = 0, dI = 0;
        if (lane < 16 && ge < EL) {
            sI = ldidx(els, ge, f64);
            dI = ldidx(eld, ge, f64);
        }
        // stage A: 4 reps x 4 edges; 8 lanes per edge load u-row + m-row (128B each)
#pragma unroll
        for (int rep = 0; rep < 4; rep++) {
            int ei = rep * 4 + quarter;
            int s = __shfl_sync(0xffffffffu, sI, ei);
            int d = __shfl_sync(0xffffffffu, dI, ei);
            uint4 uv = u2h[(size_t)s * 8 + chunk];
            uint4 mv = m2h[(size_t)d * 8 + chunk];
            *reinterpret_cast<uint4*>(&sA[w][ei * 272 + chunk * 16]) = uv;
            *reinterpret_cast<uint4*>(&sA[w][ei * 272 + 128 + chunk * 16]) = mv;
        }
        __syncwarp();

        float acc[4] = {0.f, 0.f, 0.f, 0.f};
#pragma unroll
        for (int kk = 0; kk < 8; kk++) {
            uint32_t a0[4];
            LDSM_X4(a0, a0base + kk * 32);
            MMA16816(acc, a0, bf0[kk], bf1[kk]);
        }
        __syncwarp();

        // epilogue: rows g, g+8 of the m16 tile = edges; cols 2q4, 2q4+1
        int e0 = tbase + g;
        int e1 = e0 + 8;
        float o00 = acc[0] + b0, o01 = acc[1] + b1;
        float o10 = acc[2] + b0, o11 = acc[3] + b1;
        if (e0 < EL) {
            out[(size_t)e0 * CN + col] = o00;
            if (col < 6) out[(size_t)e0 * CN + col + 1] = o01;
        }
        if (e1 < EL) {
            out[(size_t)e1 * CN + col] = o10;
            if (col < 6) out[(size_t)e1 * CN + col + 1] = o11;
        }
    }
}

// ---------------- host launch (two-stream DAG; stream/events created once) ----------------
extern "C" void kernel_launch(void* const* d_in, const int* in_sizes, int n_in,
                              void* d_out, int out_size) {
    const int* uw = (const int*)d_in[0];
    const void* unid = d_in[0];
    const void* mnid = d_in[1];
    const float* movie_x = (const float*)d_in[2];
    const void* esrc = d_in[3];
    const void* edst = d_in[4];
    const void* elsrc = d_in[5];
    const void* eldst = d_in[6];
    const float* user_emb = (const float*)d_in[7];
    const float* movie_emb = (const float*)d_in[8];
    const float* w_movie = (const float*)d_in[9];
    const float* b_movie = (const float*)d_in[10];

    int U = in_sizes[0];
    int M = in_sizes[1];
    int E = in_sizes[3];
    int EL = in_sizes[5];
    int F = in_sizes[2] / M;
    (void)n_in; (void)out_size;

    void *p_off_u, *p_off_m, *p_nbr_u, *p_nbr_m;
    void *p_x16u, *p_x16m, *p_agg16u, *p_agg16m, *p_h1u, *p_h1m, *p_u2h, *p_m2h;
    cudaGetSymbolAddress(&p_off_u, d_off_u);
    cudaGetSymbolAddress(&p_off_m, d_off_m);
    cudaGetSymbolAddress(&p_nbr_u, d_nbr_u);
    cudaGetSymbolAddress(&p_nbr_m, d_nbr_m);
    cudaGetSymbolAddress(&p_x16u, d_x16_u);
    cudaGetSymbolAddress(&p_x16m, d_x16_m);
    cudaGetSymbolAddress(&p_agg16u, d_agg16_u);
    cudaGetSymbolAddress(&p_agg16m, d_agg16_m);
    cudaGetSymbolAddress(&p_h1u, d_h1_u);
    cudaGetSymbolAddress(&p_h1m, d_h1_m);
    cudaGetSymbolAddress(&p_u2h, d_u2h);
    cudaGetSymbolAddress(&p_m2h, d_m2h);

    cudaFuncSetAttribute(k_xform_mma, cudaFuncAttributeMaxDynamicSharedMemorySize,
                         XF_SMEM);

    // one-time side stream + events (created on the first, uncaptured call)
    static cudaStream_t sB = nullptr;
    static cudaEvent_t evRoot, evFeat, evCSR, evM1, evX1, evM2;
    if (sB == nullptr) {
        cudaStreamCreateWithFlags(&sB, cudaStreamNonBlocking);
        cudaEventCreateWithFlags(&evRoot, cudaEventDisableTiming);
        cudaEventCreateWithFlags(&evFeat, cudaEventDisableTiming);
        cudaEventCreateWithFlags(&evCSR, cudaEventDisableTiming);
        cudaEventCreateWithFlags(&evM1, cudaEventDisableTiming);
        cudaEventCreateWithFlags(&evX1, cudaEventDisableTiming);
        cudaEventCreateWithFlags(&evM2, cudaEventDisableTiming);
    }

    const int* off_u = (const int*)p_off_u;
    const int* off_m = (const int*)p_off_m;
    const int* nbr_u = (const int*)p_nbr_u;
    const int* nbr_m = (const int*)p_nbr_m;

    int GG = (U * 8 + 255) / 256;
    int GM = 1024;
    int NB = (U + M + 4095) / 4096;
    const int GB = 1776;
    int XU = (U + 127) / 128, XM = (M + 127) / 128;

    // fork side stream from main
    cudaEventRecord(evRoot, 0);
    cudaStreamWaitEvent(sB, evRoot, 0);

    // stream B: CSR build chain (count -> scan -> fill)
    k_count<<<2048, 256, 0, sB>>>(uw, esrc, edst, U, E);
    k_scan_lb<<<NB, 1024, 0, sB>>>(U, M, E);
    k_fill<<<2048, 256, 0, sB>>>(uw, esrc, edst, E);
    cudaEventRecord(evCSR, sB);

    // main stream: feature prep (runs concurrent with CSR build)
    k_feat<<<GG + GM, 256>>>(uw, unid, mnid, user_emb, movie_x, w_movie,
                             b_movie, movie_emb, U, M, F, GG, GM);
    cudaEventRecord(evFeat, 0);

    // layer 1 gathers: U on main (needs CSR), M on side (needs feat)
    cudaStreamWaitEvent(0, evCSR, 0);
    cudaStreamWaitEvent(sB, evFeat, 0);
    k_gather<<<GB, 256>>>((const uint2*)p_x16m, (uint2*)p_agg16u, off_u, nbr_u, U);
    k_gather<<<GB, 256, 0, sB>>>((const uint2*)p_x16u, (uint2*)p_agg16m, off_m,
                                 nbr_m, M);
    cudaEventRecord(evM1, sB);
    cudaStreamWaitEvent(0, evM1, 0);

    // xform layer 1 (relu) -> h1 f16
    k_xform_mma<<<XU + XM, 128, XF_SMEM>>>(
        (const uint4*)p_agg16u, (const uint4*)p_x16u,
        (const uint4*)p_agg16m, (const uint4*)p_x16m,
        (const float*)d_in[14], (const float*)d_in[16], (const float*)d_in[15],
        (const float*)d_in[11], (const float*)d_in[13], (const float*)d_in[12],
        (__half*)p_h1u, (__half*)p_h1m, U, M, XU, 1);
    cudaEventRecord(evX1, 0);
    cudaStreamWaitEvent(sB, evX1, 0);

    // layer 2 gathers: U on main, M on side
    k_gather<<<GB, 256>>>((const uint2*)p_h1m, (uint2*)p_agg16u, off_u, nbr_u, U);
    k_gather<<<GB, 256, 0, sB>>>((const uint2*)p_h1u, (uint2*)p_agg16m, off_m,
                                 nbr_m, M);
    cudaEventRecord(evM2, sB);
    cudaStreamWaitEvent(0, evM2, 0);

    // xform layer 2 (no relu) -> u2h/m2h f16
    k_xform_mma<<<XU + XM, 128, XF_SMEM>>>(
        (const uint4*)p_agg16u, (const uint4*)p_h1u,
        (const uint4*)p_agg16m, (const uint4*)p_h1m,
        (const float*)d_in[20], (const float*)d_in[22], (const float*)d_in[21],
        (const float*)d_in[17], (const float*)d_in[19], (const float*)d_in[18],
        (__half*)p_u2h, (__half*)p_m2h, U, M, XU, 0);

    // classifier + scratch re-zero (main stream; end of graph)
    int GZ = (NTOT + 512 + 127) / 128;
    int GCC = 1480;
    k_classify_mma<<<GZ + GCC, 128>>>(uw, elsrc, eldst, (const float*)d_in[23],
                                      (const float*)d_in[24],
                                      (const uint4*)p_u2h, (const uint4*)p_m2h,
                                      (float*)d_out, EL, GZ, GCC);
}